// round 3
// baseline (speedup 1.0000x reference)
#include <cuda_runtime.h>

#define N 256
#define NMASK 255
#define PLANE (N * N)            // 65536
#define VOL   (N * N * N)        // 16777216

// Block: 256 threads = 8 y-lines x 32 float4x2-chunks (each thread: 8 z elems).
// Grid: b(4) * x(256) * ygroups(32) = 32768 blocks.
__global__ __launch_bounds__(256, 8)
void fd_grad_kernel(const float* __restrict__ v, float* __restrict__ out) {
    __shared__ float s[8 * N];

    const int t  = threadIdx.x;
    const int l  = t >> 5;          // line within block: 0..7
    const int q  = t & 31;          // chunk index along z (8 floats each): 0..31

    const unsigned bid = blockIdx.x;
    const int yb = bid & 31;              // y-group (8 lines each)
    const int x  = (bid >> 5) & NMASK;    // x plane
    const int b  = bid >> 13;             // batch

    const int y  = (yb << 3) | l;

    const long long bvol = (long long)b * VOL;
    const float* __restrict__ basep = v + bvol + (long long)x * PLANE;
    const long long rowoff = (long long)y * N;

    // ---- center line load (feeds gz) ----
    const float4* __restrict__ crow = (const float4*)(basep + rowoff);
    float4 c0 = crow[2 * q];
    float4 c1 = crow[2 * q + 1];

    // stash line in shared for z-straddle elements
    float4* srow4 = (float4*)(s + l * N);
    srow4[2 * q]     = c0;
    srow4[2 * q + 1] = c1;
    __syncthreads();

    const int z0 = 8 * q;
    const float sl = s[l * N + ((z0 - 1) & NMASK)];  // left of chunk
    const float sr = s[l * N + ((z0 + 8) & NMASK)];  // right of chunk

    float4 gz0, gz1;
    gz0.x = (c0.y - sl)   * 0.5f;
    gz0.y = (c0.z - c0.x) * 0.5f;
    gz0.z = (c0.w - c0.y) * 0.5f;
    gz0.w = (c1.x - c0.z) * 0.5f;
    gz1.x = (c1.y - c0.w) * 0.5f;
    gz1.y = (c1.z - c1.x) * 0.5f;
    gz1.z = (c1.w - c1.y) * 0.5f;
    gz1.w = (sr   - c1.z) * 0.5f;

    // ---- y gradient ----
    const int yp = (y + 1) & NMASK;
    const int ym = (y - 1) & NMASK;
    const float4* __restrict__ prow = (const float4*)(basep + (long long)yp * N);
    const float4* __restrict__ mrow = (const float4*)(basep + (long long)ym * N);
    float4 a0 = prow[2 * q], a1 = prow[2 * q + 1];
    float4 d0 = mrow[2 * q], d1 = mrow[2 * q + 1];
    float4 gy0, gy1;
    gy0.x = (a0.x - d0.x) * 0.5f;  gy0.y = (a0.y - d0.y) * 0.5f;
    gy0.z = (a0.z - d0.z) * 0.5f;  gy0.w = (a0.w - d0.w) * 0.5f;
    gy1.x = (a1.x - d1.x) * 0.5f;  gy1.y = (a1.y - d1.y) * 0.5f;
    gy1.z = (a1.z - d1.z) * 0.5f;  gy1.w = (a1.w - d1.w) * 0.5f;

    // ---- x gradient ----
    const int xp = (x + 1) & NMASK;
    const int xm = (x - 1) & NMASK;
    const float4* __restrict__ prowx = (const float4*)(v + bvol + (long long)xp * PLANE + rowoff);
    const float4* __restrict__ mrowx = (const float4*)(v + bvol + (long long)xm * PLANE + rowoff);
    float4 p0 = prowx[2 * q], p1 = prowx[2 * q + 1];
    float4 m0 = mrowx[2 * q], m1 = mrowx[2 * q + 1];
    float4 gx0, gx1;
    gx0.x = (p0.x - m0.x) * 0.5f;  gx0.y = (p0.y - m0.y) * 0.5f;
    gx0.z = (p0.z - m0.z) * 0.5f;  gx0.w = (p0.w - m0.w) * 0.5f;
    gx1.x = (p1.x - m1.x) * 0.5f;  gx1.y = (p1.y - m1.y) * 0.5f;
    gx1.z = (p1.z - m1.z) * 0.5f;  gx1.w = (p1.w - m1.w) * 0.5f;

    // ---- streaming stores: out[b][comp][x][y][z] ----
    float* __restrict__ ob = out + (long long)b * 3 * VOL
                                 + (long long)x * PLANE + rowoff;
    float4* o_gx = (float4*)(ob);
    float4* o_gy = (float4*)(ob + VOL);
    float4* o_gz = (float4*)(ob + 2LL * VOL);
    __stcs(&o_gx[2 * q],     gx0);
    __stcs(&o_gx[2 * q + 1], gx1);
    __stcs(&o_gy[2 * q],     gy0);
    __stcs(&o_gy[2 * q + 1], gy1);
    __stcs(&o_gz[2 * q],     gz0);
    __stcs(&o_gz[2 * q + 1], gz1);
}

extern "C" void kernel_launch(void* const* d_in, const int* in_sizes, int n_in,
                              void* d_out, int out_size) {
    const float* v = (const float*)d_in[0];
    float* out = (float*)d_out;
    // 4 batches * 256 x-planes * 32 y-groups
    dim3 grid(4 * 256 * 32);
    dim3 block(256);
    fd_grad_kernel<<<grid, block>>>(v, out);
}

// round 4
// speedup vs baseline: 1.3945x; 1.3945x over previous
#include <cuda_runtime.h>

#define N 256
#define NMASK 255
#define PLANE (N * N)            // 65536
#define VOL   (N * N * N)        // 16777216

// Block: 256 threads = 4 line-slots x 64 quads; each thread handles the same
// z-quad on TWO y-lines (l and l+4). Grid: b(4) * x(256) * ygroups(32) = 32768.
__global__ __launch_bounds__(256, 8)
void fd_grad_kernel(const float* __restrict__ v, float* __restrict__ out) {
    __shared__ float s[8 * N];

    const int t  = threadIdx.x;
    const int l  = t >> 6;          // line slot: 0..3
    const int q  = t & 63;          // float4 index along z: 0..63 (lane-contiguous)

    const unsigned bid = blockIdx.x;
    const int yb = bid & 31;              // y-group (8 lines)
    const int x  = (bid >> 5) & NMASK;    // x plane
    const int b  = bid >> 13;             // batch

    const int y0 = (yb << 3) | l;         // first line
    const int y1 = y0 + 4;                // second line (same group)
    const int l1 = l + 4;

    const long long bvol = (long long)b * VOL;
    const float* __restrict__ basep = v + bvol + (long long)x * PLANE;
    const long long row0 = (long long)y0 * N;
    const long long row1 = (long long)y1 * N;

    // ---- center lines (feed gz) ----
    float4 cA = ((const float4*)(basep + row0))[q];
    float4 cB = ((const float4*)(basep + row1))[q];

    ((float4*)(s + l  * N))[q] = cA;
    ((float4*)(s + l1 * N))[q] = cB;
    __syncthreads();

    const int zm = (4 * q - 1) & NMASK;
    const int zp = (4 * q + 4) & NMASK;
    const float slA = s[l  * N + zm], srA = s[l  * N + zp];
    const float slB = s[l1 * N + zm], srB = s[l1 * N + zp];

    float4 gzA, gzB;
    gzA.x = (cA.y - slA)  * 0.5f;
    gzA.y = (cA.z - cA.x) * 0.5f;
    gzA.z = (cA.w - cA.y) * 0.5f;
    gzA.w = (srA  - cA.z) * 0.5f;
    gzB.x = (cB.y - slB)  * 0.5f;
    gzB.y = (cB.z - cB.x) * 0.5f;
    gzB.z = (cB.w - cB.y) * 0.5f;
    gzB.w = (srB  - cB.z) * 0.5f;

    // ---- y gradient (periodic) ----
    const int ypA = (y0 + 1) & NMASK, ymA = (y0 - 1) & NMASK;
    const int ypB = (y1 + 1) & NMASK, ymB = (y1 - 1) & NMASK;
    float4 aA = ((const float4*)(basep + (long long)ypA * N))[q];
    float4 dA = ((const float4*)(basep + (long long)ymA * N))[q];
    float4 aB = ((const float4*)(basep + (long long)ypB * N))[q];
    float4 dB = ((const float4*)(basep + (long long)ymB * N))[q];
    float4 gyA, gyB;
    gyA.x = (aA.x - dA.x) * 0.5f;  gyA.y = (aA.y - dA.y) * 0.5f;
    gyA.z = (aA.z - dA.z) * 0.5f;  gyA.w = (aA.w - dA.w) * 0.5f;
    gyB.x = (aB.x - dB.x) * 0.5f;  gyB.y = (aB.y - dB.y) * 0.5f;
    gyB.z = (aB.z - dB.z) * 0.5f;  gyB.w = (aB.w - dB.w) * 0.5f;

    // ---- x gradient (periodic) ----
    const int xp = (x + 1) & NMASK;
    const int xm = (x - 1) & NMASK;
    const float* __restrict__ pp = v + bvol + (long long)xp * PLANE;
    const float* __restrict__ pm = v + bvol + (long long)xm * PLANE;
    float4 pA = ((const float4*)(pp + row0))[q];
    float4 mA = ((const float4*)(pm + row0))[q];
    float4 pB = ((const float4*)(pp + row1))[q];
    float4 mB = ((const float4*)(pm + row1))[q];
    float4 gxA, gxB;
    gxA.x = (pA.x - mA.x) * 0.5f;  gxA.y = (pA.y - mA.y) * 0.5f;
    gxA.z = (pA.z - mA.z) * 0.5f;  gxA.w = (pA.w - mA.w) * 0.5f;
    gxB.x = (pB.x - mB.x) * 0.5f;  gxB.y = (pB.y - mB.y) * 0.5f;
    gxB.z = (pB.z - mB.z) * 0.5f;  gxB.w = (pB.w - mB.w) * 0.5f;

    // ---- streaming stores: out[b][comp][x][y][z] ----
    float* __restrict__ ob = out + (long long)b * 3 * VOL + (long long)x * PLANE;
    __stcs(&((float4*)(ob            + row0))[q], gxA);
    __stcs(&((float4*)(ob            + row1))[q], gxB);
    __stcs(&((float4*)(ob +       VOL + row0))[q], gyA);
    __stcs(&((float4*)(ob +       VOL + row1))[q], gyB);
    __stcs(&((float4*)(ob + 2LL * VOL + row0))[q], gzA);
    __stcs(&((float4*)(ob + 2LL * VOL + row1))[q], gzB);
}

extern "C" void kernel_launch(void* const* d_in, const int* in_sizes, int n_in,
                              void* d_out, int out_size) {
    const float* v = (const float*)d_in[0];
    float* out = (float*)d_out;
    dim3 grid(4 * 256 * 32);
    dim3 block(256);
    fd_grad_kernel<<<grid, block>>>(v, out);
}

// round 5
// speedup vs baseline: 1.4437x; 1.0353x over previous
#include <cuda_runtime.h>

#define N 256
#define NMASK 255
#define PLANE (N * N)            // 65536
#define VOL   (N * N * N)        // 16777216
#define FULLM 0xffffffffu

struct V8 { float f0, f1, f2, f3, f4, f5, f6, f7; };

__device__ __forceinline__ V8 ldg_v8(const float* p) {
    V8 r;
    asm("ld.global.v8.f32 {%0,%1,%2,%3,%4,%5,%6,%7}, [%8];"
        : "=f"(r.f0), "=f"(r.f1), "=f"(r.f2), "=f"(r.f3),
          "=f"(r.f4), "=f"(r.f5), "=f"(r.f6), "=f"(r.f7)
        : "l"(p));
    return r;
}

__device__ __forceinline__ void stg_v8(float* p, const V8& v) {
    asm volatile("st.global.v8.f32 [%0], {%1,%2,%3,%4,%5,%6,%7,%8};"
        :: "l"(p),
           "f"(v.f0), "f"(v.f1), "f"(v.f2), "f"(v.f3),
           "f"(v.f4), "f"(v.f5), "f"(v.f6), "f"(v.f7)
        : "memory");
}

__device__ __forceinline__ V8 diff_scale(const V8& a, const V8& b) {
    V8 r;
    r.f0 = (a.f0 - b.f0) * 0.5f;  r.f1 = (a.f1 - b.f1) * 0.5f;
    r.f2 = (a.f2 - b.f2) * 0.5f;  r.f3 = (a.f3 - b.f3) * 0.5f;
    r.f4 = (a.f4 - b.f4) * 0.5f;  r.f5 = (a.f5 - b.f5) * 0.5f;
    r.f6 = (a.f6 - b.f6) * 0.5f;  r.f7 = (a.f7 - b.f7) * 0.5f;
    return r;
}

// One warp owns one full z-row (32 lanes x 8 floats = 256).
// Block: 256 threads = 8 warps = 8 y-rows.
// Grid: b(4) * x(256) * ygroups(32) = 32768 blocks.
__global__ __launch_bounds__(256)
void fd_grad_kernel(const float* __restrict__ v, float* __restrict__ out) {
    const int t    = threadIdx.x;
    const int w    = t >> 5;            // warp = row slot 0..7
    const int lane = t & 31;

    const unsigned bid = blockIdx.x;
    const int yb = bid & 31;
    const int x  = (bid >> 5) & NMASK;
    const int b  = bid >> 13;

    const int y  = (yb << 3) | w;

    const long long bvol = (long long)b * VOL;
    const float* __restrict__ basep = v + bvol + (long long)x * PLANE;
    const long long roff = (long long)y * N + lane * 8;

    // ---- loads (5 x 256-bit) ----
    const int yp = (y + 1) & NMASK;
    const int ym = (y - 1) & NMASK;
    const int xp = (x + 1) & NMASK;
    const int xm = (x - 1) & NMASK;

    V8 c = ldg_v8(basep + roff);
    V8 a = ldg_v8(basep + ((long long)yp - y) * N + roff);
    V8 d = ldg_v8(basep + ((long long)ym - y) * N + roff);
    V8 p = ldg_v8(v + bvol + (long long)xp * PLANE + roff);
    V8 m = ldg_v8(v + bvol + (long long)xm * PLANE + roff);

    // ---- gz: straddles via warp shuffle (row == one warp, periodic wrap) ----
    const float left  = __shfl_sync(FULLM, c.f7, (lane + 31) & 31); // z-1
    const float right = __shfl_sync(FULLM, c.f0, (lane + 1)  & 31); // z+8
    V8 gz;
    gz.f0 = (c.f1 - left)  * 0.5f;
    gz.f1 = (c.f2 - c.f0) * 0.5f;
    gz.f2 = (c.f3 - c.f1) * 0.5f;
    gz.f3 = (c.f4 - c.f2) * 0.5f;
    gz.f4 = (c.f5 - c.f3) * 0.5f;
    gz.f5 = (c.f6 - c.f4) * 0.5f;
    gz.f6 = (c.f7 - c.f5) * 0.5f;
    gz.f7 = (right - c.f6) * 0.5f;

    V8 gy = diff_scale(a, d);
    V8 gx = diff_scale(p, m);

    // ---- stores (3 x 256-bit): out[b][comp][x][y][z] ----
    float* __restrict__ ob = out + (long long)b * 3 * VOL
                                 + (long long)x * PLANE + roff;
    stg_v8(ob,             gx);
    stg_v8(ob + VOL,       gy);
    stg_v8(ob + 2LL * VOL, gz);
}

extern "C" void kernel_launch(void* const* d_in, const int* in_sizes, int n_in,
                              void* d_out, int out_size) {
    const float* v = (const float*)d_in[0];
    float* out = (float*)d_out;
    dim3 grid(4 * 256 * 32);
    dim3 block(256);
    fd_grad_kernel<<<grid, block>>>(v, out);
}